// round 2
// baseline (speedup 1.0000x reference)
#include <cuda_runtime.h>

#define B_WORDS 512
#define M_POS   256
#define KK      26
#define DD      128
#define PADW    27
#define ROWS_TOTAL (B_WORDS * M_POS)
#define OUT_DW  (KK * DD)      // 3328
#define OUT_TOTAL (OUT_DW + KK * KK) // 4004

// Scratch (static __device__ arrays; no runtime allocation)
__device__ float g_es[ROWS_TOTAL * KK];   // exp(scores - rowmax), 13.6 MB
__device__ float g_M [ROWS_TOTAL * KK];   // onehot - p1, 13.6 MB
__device__ float g_eT[704];               // exp(T), padded with zeros

// ---------- packed f32x2 helpers ----------
__device__ __forceinline__ unsigned long long pack2(float lo, float hi) {
    unsigned long long r;
    asm("mov.b64 %0, {%1,%2};" : "=l"(r) : "f"(lo), "f"(hi));
    return r;
}
__device__ __forceinline__ void unpack2(unsigned long long v, float& lo, float& hi) {
    asm("mov.b64 {%0,%1}, %2;" : "=f"(lo), "=f"(hi) : "l"(v));
}
__device__ __forceinline__ void ffma2(unsigned long long& d, unsigned long long a, unsigned long long b) {
    asm("fma.rn.f32x2 %0, %1, %2, %0;" : "+l"(d) : "l"(a), "l"(b));
}

// ---------- kernel 0: zero output, compute exp(T) ----------
__global__ void k0_init(const float* __restrict__ T, float* __restrict__ out) {
    int i = blockIdx.x * blockDim.x + threadIdx.x;
    if (i < OUT_TOTAL) out[i] = 0.0f;
    if (i < KK * KK)       g_eT[i] = __expf(T[i]);
    else if (i < 704)      g_eT[i] = 0.0f;
}

// ---------- kernel 1: scores = X @ W^T, es = exp(scores - rowmax) ----------
__global__ void __launch_bounds__(256) k1_scores(const float* __restrict__ X,
                                                 const float* __restrict__ Wg) {
    __shared__ __align__(16) float Ws[KK * DD];
    for (int i = threadIdx.x; i < KK * DD; i += 256) Ws[i] = Wg[i];
    __syncthreads();

    size_t r = (size_t)blockIdx.x * 256 + threadIdx.x;   // row = (word, pos) flat
    const float* x = X + r * DD;

    unsigned long long acc[KK];
#pragma unroll
    for (int k = 0; k < KK; k++) acc[k] = 0ull;

    for (int d = 0; d < DD; d += 2) {
        float2 xv = *(const float2*)(x + d);
        unsigned long long x2 = pack2(xv.x, xv.y);
#pragma unroll
        for (int k = 0; k < KK; k++) {
            unsigned long long w2 = *(const unsigned long long*)&Ws[k * DD + d]; // broadcast LDS.64
            ffma2(acc[k], x2, w2);
        }
    }

    float sv[KK];
    float mx = -3.0e38f;
#pragma unroll
    for (int k = 0; k < KK; k++) {
        float lo, hi; unpack2(acc[k], lo, hi);
        sv[k] = lo + hi;
        mx = fmaxf(mx, sv[k]);
    }
    float* es = g_es + r * (size_t)KK;
#pragma unroll
    for (int k = 0; k < KK; k++) es[k] = __expf(sv[k] - mx);
}

// ---------- kernel 2: per-word recursions + p1/p2 marginals -> M, dT ----------
// smem layout (floats): sA[256*27+8] | sB[256*27+8] | sT[704] | sb0[32] | sdT[676] | slab[256]
#define SM_A   0
#define SM_B   (M_POS * PADW + 8)
#define SM_T   (2 * (M_POS * PADW + 8))
#define SM_B0  (SM_T + 704)
#define SM_DT  (SM_B0 + 32)
#define SM_LAB (SM_DT + KK * KK)
#define SMEM2_WORDS (SM_LAB + M_POS)
#define SMEM2_BYTES (SMEM2_WORDS * 4)

__global__ void __launch_bounds__(256, 3) k2_recursion(const int* __restrict__ labels,
                                                       float* __restrict__ out) {
    extern __shared__ float sm[];
    float* sA  = sm + SM_A;
    float* sB  = sm + SM_B;
    float* sT  = sm + SM_T;
    float* sb0 = sm + SM_B0;
    float* sdT = sm + SM_DT;
    int*   slab = (int*)(sm + SM_LAB);

    const int w = blockIdx.x;
    const int tid = threadIdx.x;

    // ---- phase A: stage es into BOTH buffers (A and Bt start as es), eT, labels ----
    const float* es = g_es + (size_t)w * (M_POS * KK);
    for (int idx = tid; idx < M_POS * PADW; idx += 256) {
        int r = idx / PADW, c = idx - r * PADW;
        float v = (c < KK) ? es[r * KK + c] : 0.0f;
        sA[idx] = v; sB[idx] = v;
    }
    if (tid < 8) { sA[M_POS * PADW + tid] = 0.0f; sB[M_POS * PADW + tid] = 0.0f; }
    for (int idx = tid; idx < 704; idx += 256) sT[idx] = g_eT[idx];
    for (int idx = tid; idx < KK * KK; idx += 256) sdT[idx] = 0.0f;
    for (int idx = tid; idx < M_POS; idx += 256) slab[idx] = labels[(size_t)w * M_POS + idx];
    if (tid < 32) sb0[tid] = 0.0f;
    __syncthreads();

    const int warp = tid >> 5, lane = tid & 31;

    // ---- phase B: serial recursions (warp 0 forward, warp 1 backward) ----
    if (warp == 0) {
        // lane y holds eT[:, y]
        float eTc[KK];
#pragma unroll
        for (int j = 0; j < KK; j++) eTc[j] = sT[j * KK + lane]; // lane>=26 may read junk; never written back
        for (int i = 1; i < M_POS; i++) {
            const float* prev = sA + (i - 1) * PADW;  // A[i-1] = atilde*es (broadcast reads)
            float v0 = 0.f, v1 = 0.f;
#pragma unroll
            for (int j = 0; j < KK; j += 2) {
                v0 = fmaf(prev[j],     eTc[j],     v0);
                v1 = fmaf(prev[j + 1], eTc[j + 1], v1);
            }
            float v  = v0 + v1;                       // atilde[i] (unnormalized)
            float nw = v * sA[i * PADW + lane];       // * es[i]  -> A[i]
            if ((i & 7) == 0) {                       // periodic rescale by row max
                float t = (lane < KK) ? nw : 0.0f;
#pragma unroll
                for (int o = 16; o; o >>= 1) t = fmaxf(t, __shfl_xor_sync(0xffffffffu, t, o));
                float sc = (t > 0.0f) ? __fdividef(1.0f, t) : 1.0f;
                nw *= sc;
            }
            if (lane < KK) sA[i * PADW + lane] = nw;
            __syncwarp();
        }
    } else if (warp == 1) {
        // lane y holds eT[y, :]
        int ll = (lane < KK) ? lane : 0;
        float eTr[KK];
#pragma unroll
        for (int j = 0; j < KK; j++) eTr[j] = sT[ll * KK + j];
        for (int i = M_POS - 2; i >= 0; i--) {
            const float* nxt = sB + (i + 1) * PADW;   // Bt[i+1] = btilde*es (broadcast reads)
            float v0 = 0.f, v1 = 0.f;
#pragma unroll
            for (int j = 0; j < KK; j += 2) {
                v0 = fmaf(nxt[j],     eTr[j],     v0);
                v1 = fmaf(nxt[j + 1], eTr[j + 1], v1);
            }
            float v = v0 + v1;                        // btilde[i] (unnormalized)
            if (i == 0 && lane < KK) sb0[lane] = v;   // saved for p1[0]
            float nw = v * sB[i * PADW + lane];       // * es[i] -> Bt[i]
            if ((i & 7) == 0) {
                float t = (lane < KK) ? nw : 0.0f;
#pragma unroll
                for (int o = 16; o; o >>= 1) t = fmaxf(t, __shfl_xor_sync(0xffffffffu, t, o));
                float sc = (t > 0.0f) ? __fdividef(1.0f, t) : 1.0f;
                nw *= sc;
            }
            if (lane < KK) sB[i * PADW + lane] = nw;
            __syncwarp();
        }
    }
    __syncthreads();

    // ---- phase C: marginals. lane = b. p2[i,a,b] = A[i,a]*eT[a,b]*Bt[i+1,b]/S_i ----
    float* Mw = g_M + (size_t)w * (M_POS * KK);

    if (warp == 0) {  // p1[0] ~ A[0,k] * btilde0[k]
        float t = (lane < KK) ? sA[lane] * sb0[lane] : 0.0f;
        float s = t;
#pragma unroll
        for (int o = 16; o; o >>= 1) s += __shfl_xor_sync(0xffffffffu, s, o);
        float p = t * __fdividef(1.0f, s);
        if (lane < KK) Mw[lane] = ((slab[0] == lane) ? 1.0f : 0.0f) - p;
    }

    float eTc[KK];   // eT[a, lane]
#pragma unroll
    for (int a = 0; a < KK; a++) eTc[a] = sT[a * KK + lane];
    float ga[KK];    // Sum_i A[i,a] * f_i   (f = Bt[i+1,b]*invS)
#pragma unroll
    for (int a = 0; a < KK; a++) ga[a] = 0.0f;

    for (int i = warp; i < M_POS - 1; i += 8) {
        const float* Ar = sA + i * PADW;
        float wb = sB[(i + 1) * PADW + lane];
        float s0 = 0.f, s1 = 0.f;
#pragma unroll
        for (int a = 0; a < KK; a += 2) {
            s0 = fmaf(Ar[a],     eTc[a],     s0);
            s1 = fmaf(Ar[a + 1], eTc[a + 1], s1);
        }
        float sb = s0 + s1;                       // Sum_a A[i,a] eT[a,b]
        float contrib = (lane < KK) ? sb * wb : 0.0f;
        float S = contrib;
#pragma unroll
        for (int o = 16; o; o >>= 1) S += __shfl_xor_sync(0xffffffffu, S, o);
        float invS = __fdividef(1.0f, S);
        float f = wb * invS;
#pragma unroll
        for (int a = 0; a < KK; a++) ga[a] = fmaf(Ar[a], f, ga[a]);
        // p1[i+1, b] = sb * f  (column-marginal of p2)
        int y1 = slab[i + 1];
        if (lane < KK) {
            float p = sb * f;
            Mw[(i + 1) * KK + lane] = ((y1 == lane) ? 1.0f : 0.0f) - p;
        }
        if (lane == 0) atomicAdd(&sdT[slab[i] * KK + y1], 1.0f);  // empirical pair count
    }
    // dT[a,b] -= eT[a,b] * ga[a]
#pragma unroll
    for (int a = 0; a < KK; a++)
        if (lane < KK) atomicAdd(&sdT[a * KK + lane], -eTc[a] * ga[a]);
    __syncthreads();

    const float invB = 1.0f / (float)B_WORDS;
    for (int idx = tid; idx < KK * KK; idx += 256)
        atomicAdd(out + OUT_DW + idx, sdT[idx] * invB);
}

// ---------- kernel 3: dw = M^T @ X (mean over words) ----------
__global__ void __launch_bounds__(128) k3_dw(const float* __restrict__ X,
                                             float* __restrict__ out) {
    __shared__ __align__(16) float xs[64 * DD];            // 32 KB
    __shared__ __align__(16) unsigned long long ms2[64 * KK]; // 13 KB, M duplicated halves

    const int t  = threadIdx.x;
    const int d2 = t & 63;      // pair index over D (2 floats)
    const int kh = t >> 6;      // 0 or 1 -> k in [kh*13, kh*13+13)

    unsigned long long acc[13];
#pragma unroll
    for (int k = 0; k < 13; k++) acc[k] = 0ull;

    const size_t row0 = (size_t)blockIdx.x * 256;
    for (int ch = 0; ch < 4; ch++) {
        const size_t rbase = row0 + (size_t)ch * 64;
        // stage x tile (coalesced float4) and M tile (duplicated into both halves)
        const float4* src = (const float4*)(X + rbase * DD);
        float4* dst = (float4*)xs;
        for (int i = t; i < (64 * DD) / 4; i += 128) dst[i] = src[i];
        for (int i = t; i < 64 * KK; i += 128) {
            float m = g_M[rbase * KK + i];
            ms2[i] = pack2(m, m);
        }
        __syncthreads();
        for (int r = 0; r < 64; r++) {
            float2 xv = *(const float2*)&xs[r * DD + 2 * d2];
            unsigned long long x2 = pack2(xv.x, xv.y);
#pragma unroll
            for (int k = 0; k < 13; k++) {
                unsigned long long mm = ms2[r * KK + kh * 13 + k]; // broadcast LDS.64
                ffma2(acc[k], x2, mm);
            }
        }
        __syncthreads();
    }

    const float sc = 1.0f / (float)B_WORDS;
#pragma unroll
    for (int k = 0; k < 13; k++) {
        float lo, hi; unpack2(acc[k], lo, hi);
        int kg = kh * 13 + k;
        atomicAdd(out + kg * DD + 2 * d2,     lo * sc);
        atomicAdd(out + kg * DD + 2 * d2 + 1, hi * sc);
    }
}

// ---------- launch ----------
extern "C" void kernel_launch(void* const* d_in, const int* in_sizes, int n_in,
                              void* d_out, int out_size) {
    const float* data   = (const float*)d_in[0];   // [512,256,128] f32
    const int*   labels = (const int*)d_in[1];     // [512,256] int32 (JAX demotes int64 without x64)
    const float* W      = (const float*)d_in[2];   // [26,128] f32
    const float* T      = (const float*)d_in[3];   // [26,26] f32
    float* out = (float*)d_out;                    // [4004] f32

    cudaFuncSetAttribute(k2_recursion, cudaFuncAttributeMaxDynamicSharedMemorySize, SMEM2_BYTES);

    k0_init<<<16, 256>>>(T, out);
    k1_scores<<<512, 256>>>(data, W);
    k2_recursion<<<512, 256, SMEM2_BYTES>>>(labels, out);
    k3_dw<<<512, 128>>>(data, out);
}